// round 16
// baseline (speedup 1.0000x reference)
#include <cuda_runtime.h>
#include <cuda_fp16.h>
#include <math.h>

#define NN 100000
#define NE 1600000
#define NG 512
#define NSB 98   // scan blocks of 1024 -> covers 100352 >= NN

// ---------------- device scratch ----------------
__device__ __align__(256) __half2 g_yh[NN * 32];  // y in fp16x2: 128B/node
__device__ __align__(256) __half2 g_th[NN * 32];  // t in fp16x2: 128B/node
__device__ float g_stats[4 * 128];
__device__ float g_scale[64];
__device__ float g_shift[64];
__device__ float g_pooled[NG * 256];
__device__ float g_head1[NG * 64];
__device__ int   g_deg[NN];          // BSS zero; scan1 self-clears after use
__device__ int   g_off[NN + 1];
__device__ int   g_cursor[NN];
__device__ int   g_srcs[NE];
__device__ int   g_bsum[NSB];

// ---------------- tf32 mma (raw fp32 bits in; HW reads tf32 fields) ----------------
__device__ __forceinline__ void mma_tf32(float* d,
                                         unsigned a0, unsigned a1, unsigned a2, unsigned a3,
                                         unsigned b0, unsigned b1) {
    asm("mma.sync.aligned.m16n8k8.row.col.f32.tf32.tf32.f32 "
        "{%0,%1,%2,%3}, {%4,%5,%6,%7}, {%8,%9}, {%0,%1,%2,%3};"
        : "+f"(d[0]), "+f"(d[1]), "+f"(d[2]), "+f"(d[3])
        : "r"(a0), "r"(a1), "r"(a2), "r"(a3), "r"(b0), "r"(b1));
}

// ---------------- hist + zero fused ----------------
__global__ void hist_zero_kernel(const int* __restrict__ ei) {
    int gid = blockIdx.x * 256 + threadIdx.x;
    if (gid < 131072) g_pooled[gid] = 0.f;
    else if (gid < 131072 + 512) g_stats[gid - 131072] = 0.f;
    if (gid < NE) atomicAdd(&g_deg[ei[NE + gid]], 1);
}

// ---------------- CSR build ----------------
__global__ void scan1_kernel() {                  // <<<NSB,1024>>>
    __shared__ int wsum[32];
    int tid = threadIdx.x;
    int i = blockIdx.x * 1024 + tid;
    int v = (i < NN) ? g_deg[i] : 0;
    if (i < NN) g_deg[i] = 0;                     // self-clear for next call
    int x = v;
    #pragma unroll
    for (int o = 1; o < 32; o <<= 1) {
        int t = __shfl_up_sync(0xffffffffu, x, o);
        if ((tid & 31) >= o) x += t;
    }
    if ((tid & 31) == 31) wsum[tid >> 5] = x;
    __syncthreads();
    if (tid < 32) {
        int y = wsum[tid];
        #pragma unroll
        for (int o = 1; o < 32; o <<= 1) {
            int t = __shfl_up_sync(0xffffffffu, y, o);
            if (tid >= o) y += t;
        }
        wsum[tid] = y;
    }
    __syncthreads();
    int base = (tid >= 32) ? wsum[(tid >> 5) - 1] : 0;
    int incl = x + base;
    if (i < NN) g_off[i] = incl - v;
    if (tid == 1023) g_bsum[blockIdx.x] = incl;
}
__global__ void scan3_kernel() {                  // <<<NSB,1024>>>
    __shared__ int bs[128];
    int tid = threadIdx.x;
    if (tid < 128) bs[tid] = (tid < NSB) ? g_bsum[tid] : 0;
    __syncthreads();
    #pragma unroll
    for (int o = 1; o < 128; o <<= 1) {
        int t = 0;
        if (tid < 128 && tid >= o) t = bs[tid - o];
        __syncthreads();
        if (tid < 128) bs[tid] += t;
        __syncthreads();
    }
    int base = (blockIdx.x > 0) ? bs[blockIdx.x - 1] : 0;
    int i = blockIdx.x * 1024 + tid;
    if (i < NN) {
        int v = g_off[i] + base;
        g_off[i] = v;
        g_cursor[i] = v;
    }
    if (i == 0) g_off[NN] = NE;
}
__global__ void csr_scatter_kernel(const int* __restrict__ ei) {
    int e = blockIdx.x * 256 + threadIdx.x;
    if (e < NE) {
        int s = ei[e];
        int d = ei[NE + e];
        int p = atomicAdd(&g_cursor[d], 1);
        g_srcs[p] = s;
    }
}

// ---------------- gemm_pre (TF32 mma.sync, 8 warps M/N-split): y = X @ W1_0, fp16 store ----
// block = 64 nodes, 256 thr. warp w: rows (w&3)*16, cols (w>>2)*32, K=128
__global__ void __launch_bounds__(256) gemm_pre_kernel(
    const float* __restrict__ X, const float* __restrict__ W, int N)
{
    __shared__ float sX[64 * 132];    // fp32 bits [row][k], stride 132
    __shared__ float sW[128 * 72];    // W [k][n] direct, stride 72 (conflict-free B-frags)
    int tid = threadIdx.x, wid = tid >> 5, lid = tid & 31;
    int gi = lid >> 2, ti = lid & 3;
    int base = blockIdx.x * 64;

    const float4* Xv = (const float4*)X;
    #pragma unroll 4
    for (int i = tid; i < 2048; i += 256) {
        int row = i >> 5, q = i & 31;
        float4 v = make_float4(0.f, 0.f, 0.f, 0.f);
        int r = base + row;
        if (r < N) v = Xv[r * 32 + q];
        *(float4*)&sX[row * 132 + q * 4] = v;
    }
    const float4* Wv = (const float4*)W;
    #pragma unroll 4
    for (int i = tid; i < 2048; i += 256) {
        int k = i >> 4, q = i & 15;
        *(float4*)&sW[k * 72 + q * 4] = Wv[i];
    }
    __syncthreads();

    int arow = (wid & 3) * 16 + gi;
    int ng = (wid >> 2) * 32;
    float e[4][4];
    #pragma unroll
    for (int j = 0; j < 4; j++) { e[j][0] = 0.f; e[j][1] = 0.f; e[j][2] = 0.f; e[j][3] = 0.f; }
    #pragma unroll
    for (int t = 0; t < 16; t++) {
        int kb = t * 8;
        unsigned a0 = __float_as_uint(sX[arow * 132 + kb + ti]);
        unsigned a1 = __float_as_uint(sX[(arow + 8) * 132 + kb + ti]);
        unsigned a2 = __float_as_uint(sX[arow * 132 + kb + ti + 4]);
        unsigned a3 = __float_as_uint(sX[(arow + 8) * 132 + kb + ti + 4]);
        #pragma unroll
        for (int j = 0; j < 4; j++) {
            unsigned b0 = __float_as_uint(sW[(kb + ti) * 72 + ng + 8 * j + gi]);
            unsigned b1 = __float_as_uint(sW[(kb + ti + 4) * 72 + ng + 8 * j + gi]);
            mma_tf32(e[j], a0, a1, a2, a3, b0, b1);
        }
    }
    int r0 = base + arow, r1 = base + arow + 8;
    int cpb = ng >> 1;
    if (r0 < N) {
        #pragma unroll
        for (int j = 0; j < 4; j++)
            g_yh[r0 * 32 + cpb + 4 * j + ti] = __floats2half2_rn(e[j][0], e[j][1]);
    }
    if (r1 < N) {
        #pragma unroll
        for (int j = 0; j < 4; j++)
            g_yh[r1 * 32 + cpb + 4 * j + ti] = __floats2half2_rn(e[j][2], e[j][3]);
    }
}

// ---------------- aggregate: warp/node, t = (1+eps)y + gather(y) + b1; fp16 out; BN stats ----
__global__ void __launch_bounds__(256) aggregate_kernel(
    const float* __restrict__ eps_arr, int layer, const float* __restrict__ b1)
{
    __shared__ float ss[128];
    int tid = threadIdx.x;
    if (tid < 128) ss[tid] = 0.f;
    __syncthreads();

    int warp = (blockIdx.x * 256 + tid) >> 5;
    int lane = tid & 31;
    if (warp < NN) {
        float oe = 1.0f + __ldg(&eps_arr[layer]);
        int beg = g_off[warp], end = g_off[warp + 1];
        float2 self = __half22float2(g_yh[warp * 32 + lane]);
        float2 acc = make_float2(self.x * oe, self.y * oe);
        // software pipeline: prefetch next 32-edge index block
        int idx = (beg + lane < end) ? g_srcs[beg + lane] : 0;
        for (int bse = beg; bse < end; bse += 32) {
            int m = end - bse; if (m > 32) m = 32;
            int nb = bse + 32;
            int idx_next = (nb + lane < end) ? g_srcs[nb + lane] : 0;
            int t = 0;
            for (; t + 4 <= m; t += 4) {
                int s0 = __shfl_sync(0xffffffffu, idx, t);
                int s1 = __shfl_sync(0xffffffffu, idx, t + 1);
                int s2 = __shfl_sync(0xffffffffu, idx, t + 2);
                int s3 = __shfl_sync(0xffffffffu, idx, t + 3);
                float2 a = __half22float2(g_yh[s0 * 32 + lane]);
                float2 b = __half22float2(g_yh[s1 * 32 + lane]);
                float2 cc = __half22float2(g_yh[s2 * 32 + lane]);
                float2 d = __half22float2(g_yh[s3 * 32 + lane]);
                acc.x += (a.x + b.x) + (cc.x + d.x);
                acc.y += (a.y + b.y) + (cc.y + d.y);
            }
            for (; t < m; t++) {
                int s0 = __shfl_sync(0xffffffffu, idx, t);
                float2 a = __half22float2(g_yh[s0 * 32 + lane]);
                acc.x += a.x; acc.y += a.y;
            }
            idx = idx_next;
        }
        float2 bb = *(const float2*)&b1[2 * lane];
        acc.x += bb.x; acc.y += bb.y;
        g_th[warp * 32 + lane] = __floats2half2_rn(acc.x, acc.y);
        atomicAdd(&ss[2 * lane], acc.x);
        atomicAdd(&ss[2 * lane + 1], acc.y);
        atomicAdd(&ss[64 + 2 * lane], acc.x * acc.x);
        atomicAdd(&ss[64 + 2 * lane + 1], acc.y * acc.y);
    }
    __syncthreads();
    if (tid < 128) atomicAdd(&g_stats[layer * 128 + tid], ss[tid]);
}

// ---------------- gemm_dual (TF32 mma.sync): z=relu(bn(t)); H=relu(z@W2+b2);
//                  y_next = H@W1n (fp16 out); pool H ----------------
// block = 128 nodes, 8 warps; warp = 16-row m-tile x 64 cols (8 n-tiles), K=64 (8 k-steps)
__global__ void __launch_bounds__(256) gemm_dual_kernel(
    const float* __restrict__ W2, const float* __restrict__ B2,
    const int* __restrict__ batch, int pool_off,
    const float* __restrict__ W1n, int has_next, int N,
    int layer, const float* __restrict__ gg, const float* __restrict__ be, float ninv)
{
    __shared__ float sA[128 * 68];    // A (z, fp32 bits) -> reused for H (f32)
    __shared__ float sB2[64 * 72];    // W2 [k][n] direct, stride 72
    __shared__ float sB1[64 * 72];    // W1n [k][n] direct
    __shared__ float scs[64], shs[64], b2s[64];
    int tid = threadIdx.x, wid = tid >> 5, lid = tid & 31;
    int gi = lid >> 2, ti = lid & 3;

    if (tid < 64) {
        float mean = g_stats[layer * 128 + tid] * ninv;
        float var  = g_stats[layer * 128 + 64 + tid] * ninv - mean * mean;
        float s = gg[tid] * rsqrtf(var + 1e-5f);
        scs[tid] = s;
        shs[tid] = fmaf(-mean, s, be[tid]);
        b2s[tid] = B2[tid];
    }
    __syncthreads();

    // stage A = relu(bn(g_th)): [row][k], stride 68 (fp16 source -> fp32 smem)
    int base = blockIdx.x * 128;
    const uint2* Tb = (const uint2*)g_th;    // 8B = 4 channels (2x half2)
    #pragma unroll 2
    for (int i = tid; i < 2048; i += 256) {
        int row = i >> 4, u = i & 15;
        float4 v = make_float4(0.f, 0.f, 0.f, 0.f);
        int r = base + row;
        if (r < N) {
            uint2 tp = Tb[r * 16 + u];
            float2 t0 = __half22float2(*(__half2*)&tp.x);
            float2 t1 = __half22float2(*(__half2*)&tp.y);
            int cb = u * 4;
            v.x = fmaxf(fmaf(t0.x, scs[cb + 0], shs[cb + 0]), 0.f);
            v.y = fmaxf(fmaf(t0.y, scs[cb + 1], shs[cb + 1]), 0.f);
            v.z = fmaxf(fmaf(t1.x, scs[cb + 2], shs[cb + 2]), 0.f);
            v.w = fmaxf(fmaf(t1.y, scs[cb + 3], shs[cb + 3]), 0.f);
        }
        *(float4*)&sA[row * 68 + u * 4] = v;
    }
    // stage B2/B1 direct [k][n], float4 coalesced (raw fp32 bits)
    {
        const float4* Wv = (const float4*)W2;
        #pragma unroll 2
        for (int i = tid; i < 1024; i += 256) {
            int k = i >> 4, q = i & 15;
            *(float4*)&sB2[k * 72 + q * 4] = Wv[i];
        }
    }
    if (has_next) {
        const float4* Wv = (const float4*)W1n;
        #pragma unroll 2
        for (int i = tid; i < 1024; i += 256) {
            int k = i >> 4, q = i & 15;
            *(float4*)&sB1[k * 72 + q * 4] = Wv[i];
        }
    }
    __syncthreads();

    // MMA1: D = A @ W2, bias pre-loaded
    int arow = wid * 16 + gi;
    float d[8][4];
    #pragma unroll
    for (int j = 0; j < 8; j++) {
        float bb0 = b2s[8 * j + 2 * ti], bb1 = b2s[8 * j + 2 * ti + 1];
        d[j][0] = bb0; d[j][1] = bb1; d[j][2] = bb0; d[j][3] = bb1;
    }
    #pragma unroll
    for (int t = 0; t < 8; t++) {
        int kb = t * 8;
        unsigned a0 = __float_as_uint(sA[arow * 68 + kb + ti]);
        unsigned a1 = __float_as_uint(sA[(arow + 8) * 68 + kb + ti]);
        unsigned a2 = __float_as_uint(sA[arow * 68 + kb + ti + 4]);
        unsigned a3 = __float_as_uint(sA[(arow + 8) * 68 + kb + ti + 4]);
        #pragma unroll
        for (int j = 0; j < 8; j++) {
            unsigned b0 = __float_as_uint(sB2[(kb + ti) * 72 + 8 * j + gi]);
            unsigned b1 = __float_as_uint(sB2[(kb + ti + 4) * 72 + 8 * j + gi]);
            mma_tf32(d[j], a0, a1, a2, a3, b0, b1);
        }
    }

    // H = relu(D); overwrite own-warp rows of sA
    #pragma unroll
    for (int j = 0; j < 8; j++) {
        float h0 = fmaxf(d[j][0], 0.f), h1 = fmaxf(d[j][1], 0.f);
        float h2 = fmaxf(d[j][2], 0.f), h3 = fmaxf(d[j][3], 0.f);
        *(float2*)&sA[arow * 68 + 8 * j + 2 * ti]       = make_float2(h0, h1);
        *(float2*)&sA[(arow + 8) * 68 + 8 * j + 2 * ti] = make_float2(h2, h3);
    }
    __syncwarp();

    // MMA2: y_next = H @ W1n, write fp16
    if (has_next) {
        float e[8][4];
        #pragma unroll
        for (int j = 0; j < 8; j++) { e[j][0] = 0.f; e[j][1] = 0.f; e[j][2] = 0.f; e[j][3] = 0.f; }
        #pragma unroll
        for (int t = 0; t < 8; t++) {
            int kb = t * 8;
            unsigned a0 = __float_as_uint(sA[arow * 68 + kb + ti]);
            unsigned a1 = __float_as_uint(sA[(arow + 8) * 68 + kb + ti]);
            unsigned a2 = __float_as_uint(sA[arow * 68 + kb + ti + 4]);
            unsigned a3 = __float_as_uint(sA[(arow + 8) * 68 + kb + ti + 4]);
            #pragma unroll
            for (int j = 0; j < 8; j++) {
                unsigned b0 = __float_as_uint(sB1[(kb + ti) * 72 + 8 * j + gi]);
                unsigned b1 = __float_as_uint(sB1[(kb + ti + 4) * 72 + 8 * j + gi]);
                mma_tf32(e[j], a0, a1, a2, a3, b0, b1);
            }
        }
        int r0 = base + arow, r1 = base + arow + 8;
        if (r0 < N) {
            #pragma unroll
            for (int j = 0; j < 8; j++)
                g_yh[r0 * 32 + 4 * j + ti] = __floats2half2_rn(e[j][0], e[j][1]);
        }
        if (r1 < N) {
            #pragma unroll
            for (int j = 0; j < 8; j++)
                g_yh[r1 * 32 + 4 * j + ti] = __floats2half2_rn(e[j][2], e[j][3]);
        }
    }

    // pooling from sA H (f32), run-compressed (batch sorted)
    {
        int prow = wid * 16;
        int cp = lid;
        int bprev = -1; float p0 = 0.f, p1 = 0.f;
        #pragma unroll
        for (int j = 0; j < 16; j++) {
            int rr = base + prow + j;
            if (rr < N) {
                float2 hv = *(const float2*)&sA[(prow + j) * 68 + 2 * cp];
                int bg = batch[rr];
                if (bg != bprev) {
                    if (bprev >= 0)
                        atomicAdd((float2*)&g_pooled[bprev * 256 + pool_off + 2 * cp],
                                  make_float2(p0, p1));
                    bprev = bg; p0 = 0.f; p1 = 0.f;
                }
                p0 += hv.x; p1 += hv.y;
            }
        }
        if (bprev >= 0)
            atomicAdd((float2*)&g_pooled[bprev * 256 + pool_off + 2 * cp],
                      make_float2(p0, p1));
    }
}

// ---------------- head ----------------
__global__ void head1_kernel(const float* __restrict__ W, const float* __restrict__ B)
{
    int gph = blockIdx.x, c = threadIdx.x;   // <<<512,64>>>
    __shared__ float xs[256];
    #pragma unroll
    for (int i = c; i < 256; i += 64) xs[i] = g_pooled[gph * 256 + i];
    __syncthreads();
    float a = B[c];
    #pragma unroll 4
    for (int k = 0; k < 256; k++) a = fmaf(xs[k], __ldg(&W[k * 64 + c]), a);
    g_head1[gph * 64 + c] = a;
}

__global__ void head_bn_kernel(const float* __restrict__ g, const float* __restrict__ be)
{
    int c = blockIdx.x; int t = threadIdx.x;  // <<<64,256>>>
    __shared__ float red[256];
    float v0 = g_head1[t * 64 + c];
    float v1 = g_head1[(t + 256) * 64 + c];
    red[t] = v0 + v1;
    __syncthreads();
    for (int o = 128; o > 0; o >>= 1) { if (t < o) red[t] += red[t + o]; __syncthreads(); }
    float mean = red[0] * (1.0f / 512.0f);
    __syncthreads();
    float d0 = v0 - mean, d1 = v1 - mean;
    red[t] = d0 * d0 + d1 * d1;
    __syncthreads();
    for (int o = 128; o > 0; o >>= 1) { if (t < o) red[t] += red[t + o]; __syncthreads(); }
    if (t == 0) {
        float var = red[0] * (1.0f / 512.0f);
        float s = g[c] * rsqrtf(var + 1e-5f);
        g_scale[c] = s;
        g_shift[c] = fmaf(-mean, s, be[c]);
    }
}

__global__ void head_final_kernel(const float* __restrict__ W, const float* __restrict__ B,
                                  float* __restrict__ out)
{
    int gph = blockIdx.x; int c = threadIdx.x;   // <<<512,64>>>
    __shared__ float hn[64];
    __shared__ float logits[10];
    hn[c] = fmaxf(fmaf(g_head1[gph * 64 + c], g_scale[c], g_shift[c]), 0.f);
    __syncthreads();
    if (c < 10) {
        float a = B[c];
        #pragma unroll
        for (int k = 0; k < 64; k++) a = fmaf(hn[k], W[k * 10 + c], a);
        logits[c] = a;
    }
    __syncthreads();
    if (c == 0) {
        float m = logits[0];
        #pragma unroll
        for (int j = 1; j < 10; j++) m = fmaxf(m, logits[j]);
        float ssum = 0.f;
        #pragma unroll
        for (int j = 0; j < 10; j++) ssum += expf(logits[j] - m);
        float lse = m + logf(ssum);
        #pragma unroll
        for (int j = 0; j < 10; j++) out[gph * 10 + j] = logits[j] - lse;
    }
}

// ---------------- launch ----------------
extern "C" void kernel_launch(void* const* d_in, const int* in_sizes, int n_in,
                              void* d_out, int out_size)
{
    const float* x     = (const float*)d_in[0];
    const int*   ei    = (const int*)d_in[1];
    const int*   batch = (const int*)d_in[2];
    const float* eps   = (const float*)d_in[3];

    hist_zero_kernel<<<(NE + 255) / 256, 256>>>(ei);              // 1
    scan1_kernel<<<NSB, 1024>>>();                                // 2
    scan3_kernel<<<NSB, 1024>>>();                                // 3
    gemm_pre_kernel<<<(NN + 63) / 64, 256>>>(x, (const float*)d_in[4], NN);  // 4 (profiled)
    csr_scatter_kernel<<<(NE + 255) / 256, 256>>>(ei);            // 5

    for (int l = 0; l < 4; l++) {
        const float *b1, *gg, *be, *W2, *b2;
        if (l == 0) {
            b1 = (const float*)d_in[5];
            gg = (const float*)d_in[6]; be = (const float*)d_in[7];
            W2 = (const float*)d_in[8]; b2 = (const float*)d_in[9];
        } else {
            int j = l - 1;
            b1 = (const float*)d_in[11] + j * 64;
            gg = (const float*)d_in[12] + j * 64; be = (const float*)d_in[13] + j * 64;
            W2 = (const float*)d_in[14] + j * 64 * 64; b2 = (const float*)d_in[15] + j * 64;
        }
        const float* W1n = (l < 3) ? ((const float*)d_in[10] + l * 64 * 64) : (const float*)d_in[10];
        int has_next = (l < 3) ? 1 : 0;

        aggregate_kernel<<<(NN * 32 + 255) / 256, 256>>>(eps, l, b1);
        gemm_dual_kernel<<<(NN + 127) / 128, 256>>>(W2, b2, batch, l * 64, W1n, has_next, NN,
                                                    l, gg, be, 1.0f / (float)NN);
    }

    head1_kernel<<<NG, 64>>>((const float*)d_in[16], (const float*)d_in[17]);
    head_bn_kernel<<<64, 256>>>((const float*)d_in[18], (const float*)d_in[19]);
    head_final_kernel<<<NG, 64>>>((const float*)d_in[20], (const float*)d_in[21], (float*)d_out);
}

// round 17
// speedup vs baseline: 1.0644x; 1.0644x over previous
#include <cuda_runtime.h>
#include <cuda_fp16.h>
#include <math.h>

#define NN 100000
#define NE 1600000
#define NG 512
#define NSB 98   // scan blocks of 1024 -> covers 100352 >= NN

// ---------------- device scratch ----------------
__device__ __align__(256) __half2 g_yh[NN * 32];  // y in fp16x2: 128B/node
__device__ __align__(256) __half2 g_th[NN * 32];  // t in fp16x2: 128B/node
__device__ float g_stats[4 * 128];
__device__ float g_scale[64];
__device__ float g_shift[64];
__device__ float g_pooled[NG * 256];
__device__ float g_head1[NG * 64];
__device__ int   g_deg[NN];          // BSS zero; scan1 self-clears after use
__device__ int   g_off[NN + 1];
__device__ int   g_cursor[NN];
__device__ int   g_srcs[NE];
__device__ int   g_bsum[NSB];

// ---------------- fp16 mma m16n8k16, fp32 accumulate ----------------
__device__ __forceinline__ void mma_f16(float* d,
                                        unsigned a0, unsigned a1, unsigned a2, unsigned a3,
                                        unsigned b0, unsigned b1) {
    asm("mma.sync.aligned.m16n8k16.row.col.f32.f16.f16.f32 "
        "{%0,%1,%2,%3}, {%4,%5,%6,%7}, {%8,%9}, {%0,%1,%2,%3};"
        : "+f"(d[0]), "+f"(d[1]), "+f"(d[2]), "+f"(d[3])
        : "r"(a0), "r"(a1), "r"(a2), "r"(a3), "r"(b0), "r"(b1));
}
__device__ __forceinline__ unsigned h2u(__half2 h) { return *(unsigned*)&h; }

// ---------------- hist + zero fused ----------------
__global__ void hist_zero_kernel(const int* __restrict__ ei) {
    int gid = blockIdx.x * 256 + threadIdx.x;
    if (gid < 131072) g_pooled[gid] = 0.f;
    else if (gid < 131072 + 512) g_stats[gid - 131072] = 0.f;
    if (gid < NE) atomicAdd(&g_deg[ei[NE + gid]], 1);
}

// ---------------- CSR build ----------------
__global__ void scan1_kernel() {                  // <<<NSB,1024>>>
    __shared__ int wsum[32];
    int tid = threadIdx.x;
    int i = blockIdx.x * 1024 + tid;
    int v = (i < NN) ? g_deg[i] : 0;
    if (i < NN) g_deg[i] = 0;                     // self-clear for next call
    int x = v;
    #pragma unroll
    for (int o = 1; o < 32; o <<= 1) {
        int t = __shfl_up_sync(0xffffffffu, x, o);
        if ((tid & 31) >= o) x += t;
    }
    if ((tid & 31) == 31) wsum[tid >> 5] = x;
    __syncthreads();
    if (tid < 32) {
        int y = wsum[tid];
        #pragma unroll
        for (int o = 1; o < 32; o <<= 1) {
            int t = __shfl_up_sync(0xffffffffu, y, o);
            if (tid >= o) y += t;
        }
        wsum[tid] = y;
    }
    __syncthreads();
    int base = (tid >= 32) ? wsum[(tid >> 5) - 1] : 0;
    int incl = x + base;
    if (i < NN) g_off[i] = incl - v;
    if (tid == 1023) g_bsum[blockIdx.x] = incl;
}
__global__ void scan3_kernel() {                  // <<<NSB,1024>>>
    __shared__ int bs[128];
    int tid = threadIdx.x;
    if (tid < 128) bs[tid] = (tid < NSB) ? g_bsum[tid] : 0;
    __syncthreads();
    #pragma unroll
    for (int o = 1; o < 128; o <<= 1) {
        int t = 0;
        if (tid < 128 && tid >= o) t = bs[tid - o];
        __syncthreads();
        if (tid < 128) bs[tid] += t;
        __syncthreads();
    }
    int base = (blockIdx.x > 0) ? bs[blockIdx.x - 1] : 0;
    int i = blockIdx.x * 1024 + tid;
    if (i < NN) {
        int v = g_off[i] + base;
        g_off[i] = v;
        g_cursor[i] = v;
    }
    if (i == 0) g_off[NN] = NE;
}
__global__ void csr_scatter_kernel(const int* __restrict__ ei) {
    int e = blockIdx.x * 256 + threadIdx.x;
    if (e < NE) {
        int s = ei[e];
        int d = ei[NE + e];
        int p = atomicAdd(&g_cursor[d], 1);
        g_srcs[p] = s;
    }
}

// ---------------- gemm_pre (fp16 m16n8k16, 8 warps M/N-split): y = X @ W1_0, fp16 out ----
// block = 64 nodes, 256 thr. warp w: rows (w&3)*16, cols (w>>2)*32, K=128 (8 k-steps)
__global__ void __launch_bounds__(256) gemm_pre_kernel(
    const float* __restrict__ X, const float* __restrict__ W, int N)
{
    __shared__ __half sX[64 * 136];    // [row][k], stride 136 halves (68 words -> 4gi+ti banks)
    __shared__ __half sW[64 * 136];    // W^T [n][k], stride 136
    int tid = threadIdx.x, wid = tid >> 5, lid = tid & 31;
    int gi = lid >> 2, ti = lid & 3;
    int base = blockIdx.x * 64;

    // stage X -> fp16 [row][k]
    const float4* Xv = (const float4*)X;
    #pragma unroll 4
    for (int i = tid; i < 2048; i += 256) {
        int row = i >> 5, q = i & 31;
        float4 v = make_float4(0.f, 0.f, 0.f, 0.f);
        int r = base + row;
        if (r < N) v = Xv[r * 32 + q];
        __half2 p0 = __floats2half2_rn(v.x, v.y);
        __half2 p1 = __floats2half2_rn(v.z, v.w);
        *(uint2*)&sX[row * 136 + q * 4] = make_uint2(h2u(p0), h2u(p1));
    }
    // stage W^T: W[k][n] -> sW[n][k] fp16 (pair over k)
    #pragma unroll 4
    for (int i = tid; i < 4096; i += 256) {
        int kp = i >> 6, n = i & 63;            // kp in 0..63 (k pairs)
        float w0 = W[(2 * kp) * 64 + n];
        float w1 = W[(2 * kp + 1) * 64 + n];
        *(__half2*)&sW[n * 136 + 2 * kp] = __floats2half2_rn(w0, w1);
    }
    __syncthreads();

    int arow = (wid & 3) * 16 + gi;
    int ng = (wid >> 2) * 32;
    float e[4][4];
    #pragma unroll
    for (int j = 0; j < 4; j++) { e[j][0] = 0.f; e[j][1] = 0.f; e[j][2] = 0.f; e[j][3] = 0.f; }
    #pragma unroll
    for (int t = 0; t < 8; t++) {
        int kb = t * 16;
        unsigned a0 = *(const unsigned*)&sX[arow * 136 + kb + 2 * ti];
        unsigned a1 = *(const unsigned*)&sX[(arow + 8) * 136 + kb + 2 * ti];
        unsigned a2 = *(const unsigned*)&sX[arow * 136 + kb + 2 * ti + 8];
        unsigned a3 = *(const unsigned*)&sX[(arow + 8) * 136 + kb + 2 * ti + 8];
        #pragma unroll
        for (int j = 0; j < 4; j++) {
            int nrow = ng + 8 * j + gi;
            unsigned b0 = *(const unsigned*)&sW[nrow * 136 + kb + 2 * ti];
            unsigned b1 = *(const unsigned*)&sW[nrow * 136 + kb + 2 * ti + 8];
            mma_f16(e[j], a0, a1, a2, a3, b0, b1);
        }
    }
    int r0 = base + arow, r1 = base + arow + 8;
    int cpb = ng >> 1;
    if (r0 < N) {
        #pragma unroll
        for (int j = 0; j < 4; j++)
            g_yh[r0 * 32 + cpb + 4 * j + ti] = __floats2half2_rn(e[j][0], e[j][1]);
    }
    if (r1 < N) {
        #pragma unroll
        for (int j = 0; j < 4; j++)
            g_yh[r1 * 32 + cpb + 4 * j + ti] = __floats2half2_rn(e[j][2], e[j][3]);
    }
}

// ---------------- aggregate: warp/node, t = (1+eps)y + gather(y) + b1; fp16 out; BN stats ----
__global__ void __launch_bounds__(256) aggregate_kernel(
    const float* __restrict__ eps_arr, int layer, const float* __restrict__ b1)
{
    __shared__ float ss[128];
    int tid = threadIdx.x;
    if (tid < 128) ss[tid] = 0.f;
    __syncthreads();

    int warp = (blockIdx.x * 256 + tid) >> 5;
    int lane = tid & 31;
    if (warp < NN) {
        float oe = 1.0f + __ldg(&eps_arr[layer]);
        int beg = g_off[warp], end = g_off[warp + 1];
        float2 self = __half22float2(g_yh[warp * 32 + lane]);
        float2 acc = make_float2(self.x * oe, self.y * oe);
        int idx = (beg + lane < end) ? g_srcs[beg + lane] : 0;
        for (int bse = beg; bse < end; bse += 32) {
            int m = end - bse; if (m > 32) m = 32;
            int nb = bse + 32;
            int idx_next = (nb + lane < end) ? g_srcs[nb + lane] : 0;
            int t = 0;
            for (; t + 4 <= m; t += 4) {
                int s0 = __shfl_sync(0xffffffffu, idx, t);
                int s1 = __shfl_sync(0xffffffffu, idx, t + 1);
                int s2 = __shfl_sync(0xffffffffu, idx, t + 2);
                int s3 = __shfl_sync(0xffffffffu, idx, t + 3);
                float2 a = __half22float2(g_yh[s0 * 32 + lane]);
                float2 b = __half22float2(g_yh[s1 * 32 + lane]);
                float2 cc = __half22float2(g_yh[s2 * 32 + lane]);
                float2 d = __half22float2(g_yh[s3 * 32 + lane]);
                acc.x += (a.x + b.x) + (cc.x + d.x);
                acc.y += (a.y + b.y) + (cc.y + d.y);
            }
            for (; t < m; t++) {
                int s0 = __shfl_sync(0xffffffffu, idx, t);
                float2 a = __half22float2(g_yh[s0 * 32 + lane]);
                acc.x += a.x; acc.y += a.y;
            }
            idx = idx_next;
        }
        float2 bb = *(const float2*)&b1[2 * lane];
        acc.x += bb.x; acc.y += bb.y;
        g_th[warp * 32 + lane] = __floats2half2_rn(acc.x, acc.y);
        atomicAdd(&ss[2 * lane], acc.x);
        atomicAdd(&ss[2 * lane + 1], acc.y);
        atomicAdd(&ss[64 + 2 * lane], acc.x * acc.x);
        atomicAdd(&ss[64 + 2 * lane + 1], acc.y * acc.y);
    }
    __syncthreads();
    if (tid < 128) atomicAdd(&g_stats[layer * 128 + tid], ss[tid]);
}

// ---------------- gemm_dual (fp16 m16n8k16): z=relu(bn(t)); H=relu(z@W2+b2);
//                  y_next = H@W1n (fp16 out); pool H ----------------
// block = 128 nodes, 8 warps; warp = 16 rows x 64 cols (8 n-tiles), K=64 (4 k-steps)
__global__ void __launch_bounds__(256) gemm_dual_kernel(
    const float* __restrict__ W2, const float* __restrict__ B2,
    const int* __restrict__ batch, int pool_off,
    const float* __restrict__ W1n, int has_next, int N,
    int layer, const float* __restrict__ gg, const float* __restrict__ be, float ninv)
{
    __shared__ __half sA[128 * 72];    // z / H, [row][k], stride 72 halves (36 words -> 4gi+ti)
    __shared__ __half sB2[64 * 72];    // W2^T [n][k]
    __shared__ __half sB1[64 * 72];    // W1n^T [n][k]
    __shared__ float scs[64], shs[64], b2s[64];
    int tid = threadIdx.x, wid = tid >> 5, lid = tid & 31;
    int gi = lid >> 2, ti = lid & 3;

    if (tid < 64) {
        float mean = g_stats[layer * 128 + tid] * ninv;
        float var  = g_stats[layer * 128 + 64 + tid] * ninv - mean * mean;
        float s = gg[tid] * rsqrtf(var + 1e-5f);
        scs[tid] = s;
        shs[tid] = fmaf(-mean, s, be[tid]);
        b2s[tid] = B2[tid];
    }
    __syncthreads();

    // stage A = fp16(relu(bn(g_th))): [row][k]
    int base = blockIdx.x * 128;
    const uint2* Tb = (const uint2*)g_th;    // 8B = 4 channels
    #pragma unroll 2
    for (int i = tid; i < 2048; i += 256) {
        int row = i >> 4, u = i & 15;
        float4 v = make_float4(0.f, 0.f, 0.f, 0.f);
        int r = base + row;
        if (r < N) {
            uint2 tp = Tb[r * 16 + u];
            float2 t0 = __half22float2(*(__half2*)&tp.x);
            float2 t1 = __half22float2(*(__half2*)&tp.y);
            int cb = u * 4;
            v.x = fmaxf(fmaf(t0.x, scs[cb + 0], shs[cb + 0]), 0.f);
            v.y = fmaxf(fmaf(t0.y, scs[cb + 1], shs[cb + 1]), 0.f);
            v.z = fmaxf(fmaf(t1.x, scs[cb + 2], shs[cb + 2]), 0.f);
            v.w = fmaxf(fmaf(t1.y, scs[cb + 3], shs[cb + 3]), 0.f);
        }
        __half2 p0 = __floats2half2_rn(v.x, v.y);
        __half2 p1 = __floats2half2_rn(v.z, v.w);
        *(uint2*)&sA[row * 72 + u * 4] = make_uint2(h2u(p0), h2u(p1));
    }
    // stage B2^T / B1^T: W[k][n] -> sB[n][k] fp16 (pair over k)
    #pragma unroll 2
    for (int i = tid; i < 2048; i += 256) {
        int kp = i >> 6, n = i & 63;            // kp in 0..31
        float w0 = W2[(2 * kp) * 64 + n];
        float w1 = W2[(2 * kp + 1) * 64 + n];
        *(__half2*)&sB2[n * 72 + 2 * kp] = __floats2half2_rn(w0, w1);
    }
    if (has_next) {
        #pragma unroll 2
        for (int i = tid; i < 2048; i += 256) {
            int kp = i >> 6, n = i & 63;
            float w0 = W1n[(2 * kp) * 64 + n];
            float w1 = W1n[(2 * kp + 1) * 64 + n];
            *(__half2*)&sB1[n * 72 + 2 * kp] = __floats2half2_rn(w0, w1);
        }
    }
    __syncthreads();

    // MMA1: D = A @ W2^T, bias pre-loaded
    int arow = wid * 16 + gi;
    float d[8][4];
    #pragma unroll
    for (int j = 0; j < 8; j++) {
        float bb0 = b2s[8 * j + 2 * ti], bb1 = b2s[8 * j + 2 * ti + 1];
        d[j][0] = bb0; d[j][1] = bb1; d[j][2] = bb0; d[j][3] = bb1;
    }
    #pragma unroll
    for (int t = 0; t < 4; t++) {
        int kb = t * 16;
        unsigned a0 = *(const unsigned*)&sA[arow * 72 + kb + 2 * ti];
        unsigned a1 = *(const unsigned*)&sA[(arow + 8) * 72 + kb + 2 * ti];
        unsigned a2 = *(const unsigned*)&sA[arow * 72 + kb + 2 * ti + 8];
        unsigned a3 = *(const unsigned*)&sA[(arow + 8) * 72 + kb + 2 * ti + 8];
        #pragma unroll
        for (int j = 0; j < 8; j++) {
            int nrow = 8 * j + gi;
            unsigned b0 = *(const unsigned*)&sB2[nrow * 72 + kb + 2 * ti];
            unsigned b1 = *(const unsigned*)&sB2[nrow * 72 + kb + 2 * ti + 8];
            mma_f16(d[j], a0, a1, a2, a3, b0, b1);
        }
    }

    // H = relu(D) -> fp16, overwrite own-warp rows of sA
    #pragma unroll
    for (int j = 0; j < 8; j++) {
        __half2 h0 = __floats2half2_rn(fmaxf(d[j][0], 0.f), fmaxf(d[j][1], 0.f));
        __half2 h1 = __floats2half2_rn(fmaxf(d[j][2], 0.f), fmaxf(d[j][3], 0.f));
        *(__half2*)&sA[arow * 72 + 8 * j + 2 * ti]       = h0;
        *(__half2*)&sA[(arow + 8) * 72 + 8 * j + 2 * ti] = h1;
    }
    __syncwarp();

    // MMA2: y_next = H @ W1n^T, write fp16
    if (has_next) {
        float e[8][4];
        #pragma unroll
        for (int j = 0; j < 8; j++) { e[j][0] = 0.f; e[j][1] = 0.f; e[j][2] = 0.f; e[j][3] = 0.f; }
        #pragma unroll
        for (int t = 0; t < 4; t++) {
            int kb = t * 16;
            unsigned a0 = *(const unsigned*)&sA[arow * 72 + kb + 2 * ti];
            unsigned a1 = *(const unsigned*)&sA[(arow + 8) * 72 + kb + 2 * ti];
            unsigned a2 = *(const unsigned*)&sA[arow * 72 + kb + 2 * ti + 8];
            unsigned a3 = *(const unsigned*)&sA[(arow + 8) * 72 + kb + 2 * ti + 8];
            #pragma unroll
            for (int j = 0; j < 8; j++) {
                int nrow = 8 * j + gi;
                unsigned b0 = *(const unsigned*)&sB1[nrow * 72 + kb + 2 * ti];
                unsigned b1 = *(const unsigned*)&sB1[nrow * 72 + kb + 2 * ti + 8];
                mma_f16(e[j], a0, a1, a2, a3, b0, b1);
            }
        }
        int r0 = base + arow, r1 = base + arow + 8;
        if (r0 < N) {
            #pragma unroll
            for (int j = 0; j < 8; j++)
                g_yh[r0 * 32 + 4 * j + ti] = __floats2half2_rn(e[j][0], e[j][1]);
        }
        if (r1 < N) {
            #pragma unroll
            for (int j = 0; j < 8; j++)
                g_yh[r1 * 32 + 4 * j + ti] = __floats2half2_rn(e[j][2], e[j][3]);
        }
    }

    // pooling from sA H (fp16), run-compressed (batch sorted): warp rows wid*16..+15, lane = cpair
    {
        int prow = wid * 16;
        int cp = lid;
        int bprev = -1; float p0 = 0.f, p1 = 0.f;
        #pragma unroll
        for (int j = 0; j < 16; j++) {
            int rr = base + prow + j;
            if (rr < N) {
                float2 hv = __half22float2(*(const __half2*)&sA[(prow + j) * 72 + 2 * cp]);
                int bg = batch[rr];
                if (bg != bprev) {
                    if (bprev >= 0)
                        atomicAdd((float2*)&g_pooled[bprev * 256 + pool_off + 2 * cp],
                                  make_float2(p0, p1));
                    bprev = bg; p0 = 0.f; p1 = 0.f;
                }
                p0 += hv.x; p1 += hv.y;
            }
        }
        if (bprev >= 0)
            atomicAdd((float2*)&g_pooled[bprev * 256 + pool_off + 2 * cp],
                      make_float2(p0, p1));
    }
}

// ---------------- head ----------------
__global__ void head1_kernel(const float* __restrict__ W, const float* __restrict__ B)
{
    int gph = blockIdx.x, c = threadIdx.x;   // <<<512,64>>>
    __shared__ float xs[256];
    #pragma unroll
    for (int i = c; i < 256; i += 64) xs[i] = g_pooled[gph * 256 + i];
    __syncthreads();
    float a = B[c];
    #pragma unroll 4
    for (int k = 0; k < 256; k++) a = fmaf(xs[k], __ldg(&W[k * 64 + c]), a);
    g_head1[gph * 64 + c] = a;
}

__global__ void head_bn_kernel(const float* __restrict__ g, const float* __restrict__ be)
{
    int c = blockIdx.x; int t = threadIdx.x;  // <<<64,256>>>
    __shared__ float red[256];
    float v0 = g_head1[t * 64 + c];
    float v1 = g_head1[(t + 256) * 64 + c];
    red[t] = v0 + v1;
    __syncthreads();
    for (int o = 128; o > 0; o >>= 1) { if (t < o) red[t] += red[t + o]; __syncthreads(); }
    float mean = red[0] * (1.0f / 512.0f);
    __syncthreads();
    float d0 = v0 - mean, d1 = v1 - mean;
    red[t] = d0 * d0 + d1 * d1;
    __syncthreads();
    for (int o = 128; o > 0; o >>= 1) { if (t < o) red[t] += red[t + o]; __syncthreads(); }
    if (t == 0) {
        float var = red[0] * (1.0f / 512.0f);
        float s = g[c] * rsqrtf(var + 1e-5f);
        g_scale[c] = s;
        g_shift[c] = fmaf(-mean, s, be[c]);
    }
}

__global__ void head_final_kernel(const float* __restrict__ W, const float* __restrict__ B,
                                  float* __restrict__ out)
{
    int gph = blockIdx.x; int c = threadIdx.x;   // <<<512,64>>>
    __shared__ float hn[64];
    __shared__ float logits[10];
    hn[c] = fmaxf(fmaf(g_head1[gph * 64 + c], g_scale[c], g_shift[c]), 0.f);
    __syncthreads();
    if (c < 10) {
        float a = B[c];
        #pragma unroll
        for (int k = 0; k < 64; k++) a = fmaf(hn[k], W[k * 10 + c], a);
        logits[c] = a;
    }
    __syncthreads();
    if (c == 0) {
        float m = logits[0];
        #pragma unroll
        for (int j = 1; j < 10; j++) m = fmaxf(m, logits[j]);
        float ssum = 0.f;
        #pragma unroll
        for (int j = 0; j < 10; j++) ssum += expf(logits[j] - m);
        float lse = m + logf(ssum);
        #pragma unroll
        for (int j = 0; j < 10; j++) out[gph * 10 + j] = logits[j] - lse;
    }
}

// ---------------- launch ----------------
extern "C" void kernel_launch(void* const* d_in, const int* in_sizes, int n_in,
                              void* d_out, int out_size)
{
    const float* x     = (const float*)d_in[0];
    const int*   ei    = (const int*)d_in[1];
    const int*   batch = (const int*)d_in[2];
    const float* eps   = (const float*)d_in[3];

    hist_zero_kernel<<<(NE + 255) / 256, 256>>>(ei);              // 1
    scan1_kernel<<<NSB, 1024>>>();                                // 2
    scan3_kernel<<<NSB, 1024>>>();                                // 3
    gemm_pre_kernel<<<(NN + 63) / 64, 256>>>(x, (const float*)d_in[4], NN);  // 4 (profiled)
    csr_scatter_kernel<<<(NE + 255) / 256, 256>>>(ei);            // 5

    for (int l = 0; l < 4; l++) {
        const float *b1, *gg, *be, *W2, *b2;
        if (l == 0) {
            b1 = (const float*)d_in[5];
            gg = (const float*)d_in[6]; be = (const float*)d_in[7];
            W2 = (const float*)d_in[8]; b2 = (const float*)d_in[9];
        } else {
            int j = l - 1;
            b1 = (const float*)d_in[11] + j * 64;
            gg = (const float*)d_in[12] + j * 64; be = (const float*)d_in[13] + j * 64;
            W2 = (const float*)d_in[14] + j * 64 * 64; b2 = (const float*)d_in[15] + j * 64;
        }
        const float* W1n = (l < 3) ? ((const float*)d_in[10] + l * 64 * 64) : (const float*)d_in[10];
        int has_next = (l < 3) ? 1 : 0;

        aggregate_kernel<<<(NN * 32 + 255) / 256, 256>>>(eps, l, b1);
        gemm_dual_kernel<<<(NN + 127) / 128, 256>>>(W2, b2, batch, l * 64, W1n, has_next, NN,
                                                    l, gg, be, 1.0f / (float)NN);
    }

    head1_kernel<<<NG, 64>>>((const float*)d_in[16], (const float*)d_in[17]);
    head_bn_kernel<<<64, 256>>>((const float*)d_in[18], (const float*)d_in[19]);
    head_final_kernel<<<NG, 64>>>((const float*)d_in[20], (const float*)d_in[21], (float*)d_out);
}